// round 13
// baseline (speedup 1.0000x reference)
#include <cuda_runtime.h>
#include <cuda_fp16.h>
#include <math.h>

#define BDIM 2
#define NSEQ 2048
#define LDIM 1024
#define DDIM 1024
#define HH   16
#define HDM  64
#define BNROWS (BDIM*NSEQ)   // 4096
#define SM_SCALE 0.125f

static const long OUT1   = (long)BDIM * NSEQ * DDIM;        // 4,194,304
static const long AELEMS = (long)BDIM * HH * NSEQ * NSEQ;   // 134,217,728

typedef __half fp16;

// ---------------- device scratch (no cudaMalloc anywhere) ----------------
__device__ __align__(256) fp16 g_x16[BNROWS*LDIM];
__device__ __align__(256) fp16 g_w16[5][LDIM*DDIM];
__device__ __align__(256) fp16 g_Q16[BNROWS*DDIM];
__device__ __align__(256) fp16 g_K16[BNROWS*DDIM];
__device__ __align__(256) fp16 g_V16[BNROWS*DDIM];
__device__ __align__(256) fp16 g_G16[BNROWS*DDIM];
__device__ __align__(256) fp16 g_VG16[BNROWS*DDIM];
__device__ __align__(256) fp16 g_M16[BNROWS*DDIM];
__device__ float g_Y[BNROWS*DDIM];
__device__ float g_Afb[(size_t)BDIM*HH*NSEQ*NSEQ];  // fallback if A not in output

// ---------------- PTX helpers ----------------
__device__ __forceinline__ unsigned smem_u32(const void* p) {
    return (unsigned)__cvta_generic_to_shared(p);
}
__device__ __forceinline__ void cp16(unsigned dst, const void* src) {
    asm volatile("cp.async.ca.shared.global [%0], [%1], 16;\n" :: "r"(dst), "l"(src));
}
__device__ __forceinline__ void cp_commit() { asm volatile("cp.async.commit_group;\n" ::); }
template<int N> __device__ __forceinline__ void cp_wait() {
    asm volatile("cp.async.wait_group %0;\n" :: "n"(N));
}
__device__ __forceinline__ void ldm_x4(unsigned* d, unsigned addr) {
    asm volatile("ldmatrix.sync.aligned.m8n8.x4.shared.b16 {%0,%1,%2,%3}, [%4];"
                 : "=r"(d[0]), "=r"(d[1]), "=r"(d[2]), "=r"(d[3]) : "r"(addr));
}
__device__ __forceinline__ void ldm_x4t(unsigned* d, unsigned addr) {
    asm volatile("ldmatrix.sync.aligned.m8n8.x4.trans.shared.b16 {%0,%1,%2,%3}, [%4];"
                 : "=r"(d[0]), "=r"(d[1]), "=r"(d[2]), "=r"(d[3]) : "r"(addr));
}
__device__ __forceinline__ void mma_fp16(float* c, const unsigned* a, const unsigned* b) {
    asm volatile(
        "mma.sync.aligned.m16n8k16.row.col.f32.f16.f16.f32 "
        "{%0,%1,%2,%3},{%4,%5,%6,%7},{%8,%9},{%0,%1,%2,%3};"
        : "+f"(c[0]), "+f"(c[1]), "+f"(c[2]), "+f"(c[3])
        : "r"(a[0]), "r"(a[1]), "r"(a[2]), "r"(a[3]), "r"(b[0]), "r"(b[1]));
}
__device__ __forceinline__ unsigned pack2h(float a, float b) {
    __half2 t = __floats2half2_rn(a, b);
    return *(unsigned*)&t;
}

// SW128 XOR swizzle (byte offsets within a 1024B-aligned 128B-row tile)
#define SWZ(o) ((unsigned)(o) ^ ((((unsigned)(o)) >> 3) & 0x70))

// ---------------------------------------------------------------------------
// GEMM body: fp16 tensor-core GEMM, WARP TILE 64x64 (4 warps per 128x128 CTA
// tile), cp.async 2-stage, one sync/chunk.
// ---------------------------------------------------------------------------
template<int BM, int BN, int BK, int WM, int WN, int THREADS>
__device__ __forceinline__ void gemm_body(
    int K,
    const fp16* __restrict__ Ag, int lda,
    const fp16* __restrict__ Bg, int ldb,
    float* Cf, fp16* C16, int ldc,
    const float* bias, const float* resid, int ldr, int act)
{
    constexpr int APITCH = BK + 8;
    constexpr int BPITCH = BN + 8;
    constexpr int ABYTES = BM * APITCH * 2;
    constexpr int BBYTES = BK * BPITCH * 2;
    constexpr int STAGE  = ABYTES + BBYTES;
    constexpr int MI = WM / 16, NJ = WN / 8;

    extern __shared__ char dsm[];

    const int tid  = threadIdx.x;
    const int lane = tid & 31;
    const int warp = tid >> 5;
    const int wm = warp % (BM/WM);
    const int wn = warp / (BM/WM);
    const int m0 = wm * WM, n0 = wn * WN;
    const int rowBase = blockIdx.y * BM;
    const int colBase = blockIdx.x * BN;
    const int lrow  = lane & 15;
    const int lkoff = (lane >> 4) << 3;

    float acc[MI][NJ][4];
#pragma unroll
    for (int i = 0; i < MI; i++)
#pragma unroll
        for (int j = 0; j < NJ; j++)
#pragma unroll
            for (int q = 0; q < 4; q++) acc[i][j][q] = 0.f;

    auto load_stage = [&](int s, int k0) {
        char* base = dsm + s * STAGE;
        fp16* As = (fp16*)(base);
        fp16* Bs = (fp16*)(base + ABYTES);
        constexpr int ACH = BM * BK / 8;
#pragma unroll
        for (int t = 0; t < ACH; t += THREADS) {
            int idx = t + tid;
            int r = idx / (BK/8);
            int c = (idx % (BK/8)) * 8;
            cp16(smem_u32(As + r*APITCH + c), Ag + (long)(rowBase + r) * lda + k0 + c);
        }
        constexpr int BCH = BK * BN / 8;
#pragma unroll
        for (int t = 0; t < BCH; t += THREADS) {
            int idx = t + tid;
            int r = idx / (BN/8);
            int c = (idx % (BN/8)) * 8;
            cp16(smem_u32(Bs + r*BPITCH + c), Bg + (long)(k0 + r) * ldb + colBase + c);
        }
    };

    auto compute_stage = [&](int s) {
        char* base = dsm + s * STAGE;
        fp16* As = (fp16*)(base);
        fp16* Bs = (fp16*)(base + ABYTES);
#pragma unroll
        for (int kk = 0; kk < BK; kk += 16) {
            unsigned af[MI][4];
            unsigned bf[NJ][2];
#pragma unroll
            for (int mi = 0; mi < MI; mi++)
                ldm_x4(af[mi], smem_u32(As + (m0 + mi*16 + lrow)*APITCH + kk + lkoff));
#pragma unroll
            for (int nj = 0; nj < NJ; nj += 2)
                ldm_x4t(&bf[nj][0], smem_u32(Bs + (kk + lrow)*BPITCH + n0 + (nj + (lane>>4))*8));
#pragma unroll
            for (int mi = 0; mi < MI; mi++)
#pragma unroll
                for (int nj = 0; nj < NJ; nj++)
                    mma_fp16(acc[mi][nj], af[mi], bf[nj]);
        }
    };

    const int KT = K / BK;
    load_stage(0, 0);
    cp_commit();
    for (int kt = 0; kt < KT; kt++) {
        cp_wait<0>();
        __syncthreads();
        if (kt + 1 < KT) {
            load_stage((kt + 1) & 1, (kt + 1) * BK);
            cp_commit();
        }
        compute_stage(kt & 1);
    }

    // ---- epilogue ----
#pragma unroll
    for (int mi = 0; mi < MI; mi++) {
#pragma unroll
        for (int nj = 0; nj < NJ; nj++) {
            int c = colBase + n0 + nj*8 + 2*(lane & 3);
            float b0 = 0.f, b1 = 0.f;
            if (bias) { b0 = bias[c]; b1 = bias[c+1]; }
#pragma unroll
            for (int half = 0; half < 2; half++) {
                int r = rowBase + m0 + mi*16 + (lane >> 2) + half*8;
                float v0 = acc[mi][nj][half*2+0] + b0;
                float v1 = acc[mi][nj][half*2+1] + b1;
                if (act == 1) {
                    v0 = 1.f / (1.f + __expf(-v0));
                    v1 = 1.f / (1.f + __expf(-v1));
                }
                if (resid) {
                    v0 += resid[(long)r * ldr + c];
                    v1 += resid[(long)r * ldr + c + 1];
                }
                long off = (long)r * ldc + c;
                if (Cf) {
                    float2 o; o.x = v0; o.y = v1;
                    *(float2*)&Cf[off] = o;
                }
                if (C16) {
                    *(__half2*)&C16[off] = __floats2half2_rn(v0, v1);
                }
            }
        }
    }
}

// multiplexed 4-projection kernel (all-fp16)
struct Ptrs4 {
    const fp16* B16[4];
    const float* bias[4];
    fp16* C16[4];
    int act[4];
};

template<int BM, int BN, int BK, int WM, int WN>
__global__ __launch_bounds__((BM/WM)*(BN/WN)*32, 2)
void gemm4_kernel(int K, const fp16* __restrict__ A16,
                  int lda, int ldb, int ldc, Ptrs4 p)
{
    int z = blockIdx.z;
    gemm_body<BM,BN,BK,WM,WN,(BM/WM)*(BN/WN)*32>(
        K, A16, lda, p.B16[z], ldb,
        nullptr, p.C16[z], ldc, p.bias[z], nullptr, 0, p.act[z]);
}

// single GEMM (out projection): fp32 output + bias + residual
template<int BM, int BN, int BK, int WM, int WN>
__global__ __launch_bounds__((BM/WM)*(BN/WN)*32, 2)
void gemm1_kernel(int K,
                  const fp16* __restrict__ A16, int lda,
                  const fp16* __restrict__ B16, int ldb,
                  float* Cf, int ldc,
                  const float* bias, const float* resid, int ldr)
{
    gemm_body<BM,BN,BK,WM,WN,(BM/WM)*(BN/WN)*32>(
        K, A16, lda, B16, ldb,
        Cf, nullptr, ldc, bias, resid, ldr, 0);
}

constexpr int stage_bytes_h(int BM, int BN, int BK) {
    return (BM * (BK + 8) * 2) + (BK * (BN + 8) * 2);
}

// ---------------------------------------------------------------------------
// Two-pass fused attention, all-fp16. Pass-1 exp via h2exp (fp16x2 MUFU) —
// denominator rounding averages out over 2048 terms. Pass-2 exp fp32 (A
// accuracy). smem 81920B: Q [0,16384); stage s at 16384+s*32768 (K,V).
// ---------------------------------------------------------------------------
__global__ __launch_bounds__(256, 2)
void attn_kernel(const fp16* __restrict__ Qg, const fp16* __restrict__ Kg,
                 const fp16* __restrict__ Vg,
                 float* __restrict__ Ag, fp16* __restrict__ Mg)
{
    extern __shared__ char sm[];
    const unsigned sb = smem_u32(sm);
    const int tid = threadIdx.x, lane = tid & 31, warp = tid >> 5;
    const int bh = blockIdx.y, bb = bh >> 4, hh = bh & 15;
    const int q0 = blockIdx.x * 128;
    const long qrow = (long)bb * NSEQ + q0;
    const fp16* Q = Qg + qrow * DDIM + hh * HDM;
    const fp16* K = Kg + (long)bb * NSEQ * DDIM + hh * HDM;
    const fp16* V = Vg + (long)bb * NSEQ * DDIM + hh * HDM;
    float* Arow = Ag + ((long)bh * NSEQ + q0) * NSEQ;

    const int lrow = lane & 15, lk = (lane >> 4) * 8;

    auto loadQ = [&]() {
        for (int t = tid; t < 1024; t += 256) {
            int r = t >> 3, c = (t & 7) * 8;
            cp16(sb + SWZ(r * 128 + c * 2), Q + (long)r * DDIM + c);
        }
    };
    auto loadK = [&](unsigned dst, int key0) {
        for (int t = tid; t < 1024; t += 256) {
            int r = t >> 3, c = (t & 7) * 8;
            cp16(dst + SWZ(r * 128 + c * 2), K + (long)(key0 + r) * DDIM + c);
        }
    };
    auto loadV = [&](unsigned dst, int key0) {
        for (int t = tid; t < 1024; t += 256) {
            int r = t >> 3, c = (t & 7) * 8;
            cp16(dst + SWZ(r * 128 + c * 2), V + (long)(key0 + r) * DDIM + c);
        }
    };

#define STG(s) (sb + 16384u + (unsigned)(s) * 32768u)

    loadQ();
    loadK(STG(0), 0);
    cp_commit(); cp_wait<0>(); __syncthreads();

    unsigned aq[4][4];
#pragma unroll
    for (int kk = 0; kk < 4; kk++)
        ldm_x4(aq[kk], sb + SWZ((warp*16 + lrow) * 128 + (kk*16 + lk) * 2));

    auto computeS = [&](unsigned kbase, int kg, float (&c)[2][4]) {
#pragma unroll
        for (int kk = 0; kk < 4; kk++) {
            unsigned rh[4];
            ldm_x4(rh, kbase + SWZ((kg*16 + lrow) * 128 + (kk*16 + lk) * 2));
            unsigned b0[2] = {rh[0], rh[2]}, b1[2] = {rh[1], rh[3]};
            mma_fp16(c[0], aq[kk], b0);
            mma_fp16(c[1], aq[kk], b1);
        }
    };

    // ---- pass 1: S -> row sums of exp (h2exp, fp16x2) ----
    float lsum0 = 0.f, lsum1 = 0.f;
    for (int kt = 0; kt < 16; kt++) {
        unsigned cur = STG(kt & 1);
        if (kt < 15) {
            loadK(STG((kt + 1) & 1), (kt + 1) * 128);
            cp_commit();
        }
#pragma unroll 1
        for (int kg = 0; kg < 8; kg++) {
            float c[2][4] = {};
            computeS(cur, kg, c);
            float2 e0 = __half22float2(h2exp(__floats2half2_rn(c[0][0]*SM_SCALE, c[0][1]*SM_SCALE)));
            float2 e1 = __half22float2(h2exp(__floats2half2_rn(c[1][0]*SM_SCALE, c[1][1]*SM_SCALE)));
            float2 e2 = __half22float2(h2exp(__floats2half2_rn(c[0][2]*SM_SCALE, c[0][3]*SM_SCALE)));
            float2 e3 = __half22float2(h2exp(__floats2half2_rn(c[1][2]*SM_SCALE, c[1][3]*SM_SCALE)));
            lsum0 += e0.x + e0.y + e1.x + e1.y;
            lsum1 += e2.x + e2.y + e3.x + e3.y;
        }
        if (kt < 15) { cp_wait<0>(); __syncthreads(); }
    }

    lsum0 += __shfl_xor_sync(0xffffffff, lsum0, 1);
    lsum0 += __shfl_xor_sync(0xffffffff, lsum0, 2);
    lsum1 += __shfl_xor_sync(0xffffffff, lsum1, 1);
    lsum1 += __shfl_xor_sync(0xffffffff, lsum1, 2);
    float invl0 = 1.f / lsum0;
    float invl1 = 1.f / lsum1;

    // ---- pass 2: recompute S, fp32 exp, write normalized A, fused PV ----
    __syncthreads();
    loadK(STG(0), 0);
    loadV(STG(0) + 16384, 0);
    cp_commit(); cp_wait<0>(); __syncthreads();

    float Macc[8][4] = {};
    for (int kt = 0; kt < 16; kt++) {
        unsigned stg = STG(kt & 1);
        if (kt < 15) {
            unsigned pre = STG((kt + 1) & 1);
            loadK(pre, (kt + 1) * 128);
            loadV(pre + 16384, (kt + 1) * 128);
            cp_commit();
        }
        unsigned Vs = stg + 16384;
#pragma unroll 1
        for (int kg = 0; kg < 8; kg++) {
            float c[2][4] = {};
            computeS(stg, kg, c);
            float p[2][4];
#pragma unroll
            for (int nj = 0; nj < 2; nj++) {
                p[nj][0] = __expf(c[nj][0] * SM_SCALE) * invl0;
                p[nj][1] = __expf(c[nj][1] * SM_SCALE) * invl0;
                p[nj][2] = __expf(c[nj][2] * SM_SCALE) * invl1;
                p[nj][3] = __expf(c[nj][3] * SM_SCALE) * invl1;
            }
            long colb = (long)kt * 128 + kg * 16 + 2 * (lane & 3);
            long r0 = warp * 16 + (lane >> 2);
            float2 w;
            w.x = p[0][0]; w.y = p[0][1]; *(float2*)&Arow[r0*NSEQ + colb]           = w;
            w.x = p[1][0]; w.y = p[1][1]; *(float2*)&Arow[r0*NSEQ + colb + 8]       = w;
            w.x = p[0][2]; w.y = p[0][3]; *(float2*)&Arow[(r0+8)*NSEQ + colb]       = w;
            w.x = p[1][2]; w.y = p[1][3]; *(float2*)&Arow[(r0+8)*NSEQ + colb + 8]   = w;
            unsigned pa[4];
            pa[0] = pack2h(p[0][0], p[0][1]);
            pa[1] = pack2h(p[0][2], p[0][3]);
            pa[2] = pack2h(p[1][0], p[1][1]);
            pa[3] = pack2h(p[1][2], p[1][3]);
#pragma unroll
            for (int njp = 0; njp < 4; njp++) {
                unsigned bv[4];
                ldm_x4t(bv, Vs + SWZ((kg*16 + lrow) * 128 + ((njp*2 + (lane>>4)) * 8) * 2));
                unsigned b0[2] = {bv[0], bv[1]}, b1[2] = {bv[2], bv[3]};
                mma_fp16(Macc[njp*2],     pa, b0);
                mma_fp16(Macc[njp*2 + 1], pa, b1);
            }
        }
        if (kt < 15) { cp_wait<0>(); __syncthreads(); }
    }

    // ---- epilogue: M -> fp16 ----
    long mrow0 = qrow + warp * 16 + (lane >> 2);
#pragma unroll
    for (int njv = 0; njv < 8; njv++) {
        int col = hh * HDM + njv * 8 + 2 * (lane & 3);
        *(__half2*)&Mg[mrow0 * DDIM + col] =
            __floats2half2_rn(Macc[njv][0], Macc[njv][1]);
        *(__half2*)&Mg[(mrow0 + 8) * DDIM + col] =
            __floats2half2_rn(Macc[njv][2], Macc[njv][3]);
    }
#undef STG
}

// ---------------- elementwise kernels ----------------
__device__ __forceinline__ void conv_body(const float* __restrict__ s,
                                          fp16* __restrict__ d, long i)
{
    float4 v = *(const float4*)(s + i);
    *(__half2*)(d + i)     = __floats2half2_rn(v.x, v.y);
    *(__half2*)(d + i + 2) = __floats2half2_rn(v.z, v.w);
}

__global__ void conv_kernel(const float* __restrict__ s, fp16* __restrict__ d)
{
    long i = ((long)blockIdx.x * blockDim.x + threadIdx.x) * 4;
    conv_body(s, d, i);
}

struct ConvP { const float* s[5]; fp16* d[5]; };
__global__ void conv_multi_kernel(ConvP p)
{
    int z = blockIdx.z;
    long i = ((long)blockIdx.x * blockDim.x + threadIdx.x) * 4;
    conv_body(p.s[z], p.d[z], i);
}

// VG = V16 * G16 (G already post-sigmoid) -> fp16
__global__ void vg_kernel(const fp16* __restrict__ V, const fp16* __restrict__ G,
                          fp16* __restrict__ h)
{
    long i = ((long)blockIdx.x * blockDim.x + threadIdx.x) * 8;
    float4 v = *(const float4*)(V + i);   // 8 halves
    float4 g = *(const float4*)(G + i);
    __half2* vp = (__half2*)&v;
    __half2* gp = (__half2*)&g;
    float4 o;
    __half2* op = (__half2*)&o;
#pragma unroll
    for (int j = 0; j < 4; j++) op[j] = __hmul2(vp[j], gp[j]);
    *(float4*)(h + i) = o;
}

// LayerNorm over last dim (1024)
__global__ void ln_kernel(const float* __restrict__ Y,
                          const float* __restrict__ gamma,
                          const float* __restrict__ beta,
                          float* __restrict__ out)
{
    __shared__ float red[256];
    int row = blockIdx.x, tid = threadIdx.x;
    const float4* y4 = (const float4*)(Y + (long)row * DDIM);
    float4 v = y4[tid];

    red[tid] = v.x + v.y + v.z + v.w; __syncthreads();
    for (int o = 128; o > 0; o >>= 1) {
        if (tid < o) red[tid] += red[tid + o];
        __syncthreads();
    }
    float mean = red[0] * (1.f / DDIM);
    __syncthreads();

    float d0 = v.x - mean, d1 = v.y - mean, d2 = v.z - mean, d3 = v.w - mean;
    red[tid] = d0*d0 + d1*d1 + d2*d2 + d3*d3; __syncthreads();
    for (int o = 128; o > 0; o >>= 1) {
        if (tid < o) red[tid] += red[tid + o];
        __syncthreads();
    }
    float var = red[0] * (1.f / DDIM);
    float inv = rsqrtf(var + 1e-5f);

    float4 g  = ((const float4*)gamma)[tid];
    float4 bt = ((const float4*)beta)[tid];
    float4 o4;
    o4.x = g.x * (d0 * inv) + bt.x;
    o4.y = g.y * (d1 * inv) + bt.y;
    o4.z = g.z * (d2 * inv) + bt.z;
    o4.w = g.w * (d3 * inv) + bt.w;
    ((float4*)(out + (long)row * DDIM))[tid] = o4;
}

extern "C" void kernel_launch(void* const* d_in, const int* in_sizes, int n_in,
                              void* d_out, int out_size)
{
    const float* x     = (const float*)d_in[0];
    const float* Wq    = (const float*)d_in[1];
    const float* bq    = (const float*)d_in[2];
    const float* Wk    = (const float*)d_in[3];
    const float* bk    = (const float*)d_in[4];
    const float* Wv    = (const float*)d_in[5];
    const float* bv    = (const float*)d_in[6];
    const float* Wg    = (const float*)d_in[7];
    const float* bg    = (const float*)d_in[8];
    const float* Wp    = (const float*)d_in[9];
    const float* bp    = (const float*)d_in[10];
    const float* gamma = (const float*)d_in[11];
    const float* beta  = (const float*)d_in[12];
    float* outp = (float*)d_out;

    fp16 *x16, *w16, *Q16, *K16, *V16, *G16, *VG16, *M16;
    float *Y, *Afb;
    cudaGetSymbolAddress((void**)&x16,  g_x16);
    cudaGetSymbolAddress((void**)&w16,  g_w16);
    cudaGetSymbolAddress((void**)&Q16,  g_Q16);
    cudaGetSymbolAddress((void**)&K16,  g_K16);
    cudaGetSymbolAddress((void**)&V16,  g_V16);
    cudaGetSymbolAddress((void**)&G16,  g_G16);
    cudaGetSymbolAddress((void**)&VG16, g_VG16);
    cudaGetSymbolAddress((void**)&M16,  g_M16);
    cudaGetSymbolAddress((void**)&Y,    g_Y);
    cudaGetSymbolAddress((void**)&Afb,  g_Afb);

    float* A = ((long)out_size >= OUT1 + AELEMS) ? (outp + OUT1) : Afb;

    const long WSZ = (long)LDIM * DDIM;
    const long XHALF = (long)BNROWS * LDIM / 2;

    // launches 0-1: x -> fp16 (two halves, keeps attn at ncu launch index 5)
    conv_kernel<<<XHALF/1024, 256>>>(x, x16);
    conv_kernel<<<XHALF/1024, 256>>>(x + XHALF, x16 + XHALF);

    // launch 2: all 5 weights -> fp16
    {
        ConvP p;
        p.s[0] = Wq; p.d[0] = w16 + 0*WSZ;
        p.s[1] = Wk; p.d[1] = w16 + 1*WSZ;
        p.s[2] = Wv; p.d[2] = w16 + 2*WSZ;
        p.s[3] = Wg; p.d[3] = w16 + 3*WSZ;
        p.s[4] = Wp; p.d[4] = w16 + 4*WSZ;
        dim3 g(WSZ/1024, 1, 5);
        conv_multi_kernel<<<g, 256>>>(p);
    }

    constexpr int SM_PROJ = 2 * stage_bytes_h(128, 128, 32);   // 37888
    constexpr int SM_ATTN = 81920;

    cudaFuncSetAttribute(gemm4_kernel<128,128,32,64,64>,
                         cudaFuncAttributeMaxDynamicSharedMemorySize, SM_PROJ);
    cudaFuncSetAttribute(gemm1_kernel<128,128,32,64,64>,
                         cudaFuncAttributeMaxDynamicSharedMemorySize, SM_PROJ);
    cudaFuncSetAttribute(attn_kernel,
                         cudaFuncAttributeMaxDynamicSharedMemorySize, SM_ATTN);

    // launch 3: fused fp16 projections (Q, K, V, sigmoid-G), 64x64 warp tiles
    {
        Ptrs4 p;
        p.B16[0] = w16 + 0*WSZ; p.bias[0] = bq; p.C16[0] = Q16; p.act[0] = 0;
        p.B16[1] = w16 + 1*WSZ; p.bias[1] = bk; p.C16[1] = K16; p.act[1] = 0;
        p.B16[2] = w16 + 2*WSZ; p.bias[2] = bv; p.C16[2] = V16; p.act[2] = 0;
        p.B16[3] = w16 + 3*WSZ; p.bias[3] = bg; p.C16[3] = G16; p.act[3] = 1;
        dim3 grid(DDIM/128, BNROWS/128, 4);
        gemm4_kernel<128,128,32,64,64><<<grid, 128, SM_PROJ>>>(
            LDIM, x16, LDIM, DDIM, DDIM, p);
    }

    // launch 4: VG = V * G
    vg_kernel<<<(BNROWS*(long)DDIM)/2048, 256>>>(V16, G16, VG16);

    // launch 5: two-pass fp16 attention (ncu -s 5 lands here)
    {
        dim3 grid(NSEQ/128, BDIM*HH);
        attn_kernel<<<grid, 256, SM_ATTN>>>(Q16, K16, VG16, A, M16);
    }

    // launch 6: Y = x + M @ Wp + bp
    {
        dim3 grid(DDIM/128, BNROWS/128, 1);
        gemm1_kernel<128,128,32,64,64><<<grid, 128, SM_PROJ>>>(
            DDIM, M16, DDIM, w16 + 4*WSZ, DDIM,
            Y, DDIM, bp, x, DDIM);
    }

    // launch 7: LayerNorm -> out
    ln_kernel<<<BNROWS, 256>>>(Y, gamma, beta, outp);
}

// round 14
// speedup vs baseline: 1.0198x; 1.0198x over previous
#include <cuda_runtime.h>
#include <cuda_fp16.h>
#include <math.h>

#define BDIM 2
#define NSEQ 2048
#define LDIM 1024
#define DDIM 1024
#define HH   16
#define HDM  64
#define BNROWS (BDIM*NSEQ)   // 4096
#define SM_SCALE 0.125f

static const long OUT1   = (long)BDIM * NSEQ * DDIM;        // 4,194,304
static const long AELEMS = (long)BDIM * HH * NSEQ * NSEQ;   // 134,217,728

typedef __half fp16;

// ---------------- device scratch (no cudaMalloc anywhere) ----------------
__device__ __align__(256) fp16 g_x16[BNROWS*LDIM];
__device__ __align__(256) fp16 g_w16[5][LDIM*DDIM];
__device__ __align__(256) fp16 g_Q16[BNROWS*DDIM];
__device__ __align__(256) fp16 g_K16[BNROWS*DDIM];
__device__ __align__(256) fp16 g_V16[BNROWS*DDIM];
__device__ __align__(256) fp16 g_G16[BNROWS*DDIM];
__device__ __align__(256) fp16 g_VG16[BNROWS*DDIM];
__device__ __align__(256) fp16 g_M16[BNROWS*DDIM];
__device__ float g_Y[BNROWS*DDIM];
__device__ float g_Afb[(size_t)BDIM*HH*NSEQ*NSEQ];  // fallback if A not in output

// ---------------- PTX helpers ----------------
__device__ __forceinline__ unsigned smem_u32(const void* p) {
    return (unsigned)__cvta_generic_to_shared(p);
}
__device__ __forceinline__ void cp16(unsigned dst, const void* src) {
    asm volatile("cp.async.ca.shared.global [%0], [%1], 16;\n" :: "r"(dst), "l"(src));
}
__device__ __forceinline__ void cp_commit() { asm volatile("cp.async.commit_group;\n" ::); }
template<int N> __device__ __forceinline__ void cp_wait() {
    asm volatile("cp.async.wait_group %0;\n" :: "n"(N));
}
__device__ __forceinline__ void ldm_x4(unsigned* d, unsigned addr) {
    asm volatile("ldmatrix.sync.aligned.m8n8.x4.shared.b16 {%0,%1,%2,%3}, [%4];"
                 : "=r"(d[0]), "=r"(d[1]), "=r"(d[2]), "=r"(d[3]) : "r"(addr));
}
__device__ __forceinline__ void ldm_x4t(unsigned* d, unsigned addr) {
    asm volatile("ldmatrix.sync.aligned.m8n8.x4.trans.shared.b16 {%0,%1,%2,%3}, [%4];"
                 : "=r"(d[0]), "=r"(d[1]), "=r"(d[2]), "=r"(d[3]) : "r"(addr));
}
__device__ __forceinline__ void mma_fp16(float* c, const unsigned* a, const unsigned* b) {
    asm volatile(
        "mma.sync.aligned.m16n8k16.row.col.f32.f16.f16.f32 "
        "{%0,%1,%2,%3},{%4,%5,%6,%7},{%8,%9},{%0,%1,%2,%3};"
        : "+f"(c[0]), "+f"(c[1]), "+f"(c[2]), "+f"(c[3])
        : "r"(a[0]), "r"(a[1]), "r"(a[2]), "r"(a[3]), "r"(b[0]), "r"(b[1]));
}
__device__ __forceinline__ unsigned pack2h(float a, float b) {
    __half2 t = __floats2half2_rn(a, b);
    return *(unsigned*)&t;
}

// SW128 XOR swizzle (byte offsets within a 1024B-aligned 128B-row tile)
#define SWZ(o) ((unsigned)(o) ^ ((((unsigned)(o)) >> 3) & 0x70))

// ---------------------------------------------------------------------------
// GEMM body: fp16 tensor-core GEMM, warp tile 64x32 (proven round-12 config),
// cp.async 2-stage, one sync/chunk.
// ---------------------------------------------------------------------------
template<int BM, int BN, int BK, int WM, int WN, int THREADS>
__device__ __forceinline__ void gemm_body(
    int K,
    const fp16* __restrict__ Ag, int lda,
    const fp16* __restrict__ Bg, int ldb,
    float* Cf, fp16* C16, int ldc,
    const float* bias, const float* resid, int ldr, int act)
{
    constexpr int APITCH = BK + 8;
    constexpr int BPITCH = BN + 8;
    constexpr int ABYTES = BM * APITCH * 2;
    constexpr int BBYTES = BK * BPITCH * 2;
    constexpr int STAGE  = ABYTES + BBYTES;
    constexpr int MI = WM / 16, NJ = WN / 8;

    extern __shared__ char dsm[];

    const int tid  = threadIdx.x;
    const int lane = tid & 31;
    const int warp = tid >> 5;
    const int wm = warp % (BM/WM);
    const int wn = warp / (BM/WM);
    const int m0 = wm * WM, n0 = wn * WN;
    const int rowBase = blockIdx.y * BM;
    const int colBase = blockIdx.x * BN;
    const int lrow  = lane & 15;
    const int lkoff = (lane >> 4) << 3;

    float acc[MI][NJ][4];
#pragma unroll
    for (int i = 0; i < MI; i++)
#pragma unroll
        for (int j = 0; j < NJ; j++)
#pragma unroll
            for (int q = 0; q < 4; q++) acc[i][j][q] = 0.f;

    auto load_stage = [&](int s, int k0) {
        char* base = dsm + s * STAGE;
        fp16* As = (fp16*)(base);
        fp16* Bs = (fp16*)(base + ABYTES);
        constexpr int ACH = BM * BK / 8;
#pragma unroll
        for (int t = 0; t < ACH; t += THREADS) {
            int idx = t + tid;
            int r = idx / (BK/8);
            int c = (idx % (BK/8)) * 8;
            cp16(smem_u32(As + r*APITCH + c), Ag + (long)(rowBase + r) * lda + k0 + c);
        }
        constexpr int BCH = BK * BN / 8;
#pragma unroll
        for (int t = 0; t < BCH; t += THREADS) {
            int idx = t + tid;
            int r = idx / (BN/8);
            int c = (idx % (BN/8)) * 8;
            cp16(smem_u32(Bs + r*BPITCH + c), Bg + (long)(k0 + r) * ldb + colBase + c);
        }
    };

    auto compute_stage = [&](int s) {
        char* base = dsm + s * STAGE;
        fp16* As = (fp16*)(base);
        fp16* Bs = (fp16*)(base + ABYTES);
#pragma unroll
        for (int kk = 0; kk < BK; kk += 16) {
            unsigned af[MI][4];
            unsigned bf[NJ][2];
#pragma unroll
            for (int mi = 0; mi < MI; mi++)
                ldm_x4(af[mi], smem_u32(As + (m0 + mi*16 + lrow)*APITCH + kk + lkoff));
#pragma unroll
            for (int nj = 0; nj < NJ; nj += 2)
                ldm_x4t(&bf[nj][0], smem_u32(Bs + (kk + lrow)*BPITCH + n0 + (nj + (lane>>4))*8));
#pragma unroll
            for (int mi = 0; mi < MI; mi++)
#pragma unroll
                for (int nj = 0; nj < NJ; nj++)
                    mma_fp16(acc[mi][nj], af[mi], bf[nj]);
        }
    };

    const int KT = K / BK;
    load_stage(0, 0);
    cp_commit();
    for (int kt = 0; kt < KT; kt++) {
        cp_wait<0>();
        __syncthreads();
        if (kt + 1 < KT) {
            load_stage((kt + 1) & 1, (kt + 1) * BK);
            cp_commit();
        }
        compute_stage(kt & 1);
    }

    // ---- epilogue ----
#pragma unroll
    for (int mi = 0; mi < MI; mi++) {
#pragma unroll
        for (int nj = 0; nj < NJ; nj++) {
            int c = colBase + n0 + nj*8 + 2*(lane & 3);
            float b0 = 0.f, b1 = 0.f;
            if (bias) { b0 = bias[c]; b1 = bias[c+1]; }
#pragma unroll
            for (int half = 0; half < 2; half++) {
                int r = rowBase + m0 + mi*16 + (lane >> 2) + half*8;
                float v0 = acc[mi][nj][half*2+0] + b0;
                float v1 = acc[mi][nj][half*2+1] + b1;
                if (act == 1) {
                    v0 = 1.f / (1.f + __expf(-v0));
                    v1 = 1.f / (1.f + __expf(-v1));
                }
                if (resid) {
                    v0 += resid[(long)r * ldr + c];
                    v1 += resid[(long)r * ldr + c + 1];
                }
                long off = (long)r * ldc + c;
                if (Cf) {
                    float2 o; o.x = v0; o.y = v1;
                    *(float2*)&Cf[off] = o;
                }
                if (C16) {
                    *(__half2*)&C16[off] = __floats2half2_rn(v0, v1);
                }
            }
        }
    }
}

// multiplexed 4-projection kernel (all-fp16)
struct Ptrs4 {
    const fp16* B16[4];
    const float* bias[4];
    fp16* C16[4];
    int act[4];
};

template<int BM, int BN, int BK, int WM, int WN>
__global__ __launch_bounds__((BM/WM)*(BN/WN)*32, 2)
void gemm4_kernel(int K, const fp16* __restrict__ A16,
                  int lda, int ldb, int ldc, Ptrs4 p)
{
    int z = blockIdx.z;
    gemm_body<BM,BN,BK,WM,WN,(BM/WM)*(BN/WN)*32>(
        K, A16, lda, p.B16[z], ldb,
        nullptr, p.C16[z], ldc, p.bias[z], nullptr, 0, p.act[z]);
}

// single GEMM (out projection): fp32 output + bias + residual
template<int BM, int BN, int BK, int WM, int WN>
__global__ __launch_bounds__((BM/WM)*(BN/WN)*32, 2)
void gemm1_kernel(int K,
                  const fp16* __restrict__ A16, int lda,
                  const fp16* __restrict__ B16, int ldb,
                  float* Cf, int ldc,
                  const float* bias, const float* resid, int ldr)
{
    gemm_body<BM,BN,BK,WM,WN,(BM/WM)*(BN/WN)*32>(
        K, A16, lda, B16, ldb,
        Cf, nullptr, ldc, bias, resid, ldr, 0);
}

constexpr int stage_bytes_h(int BM, int BN, int BK) {
    return (BM * (BK + 8) * 2) + (BK * (BN + 8) * 2);
}

// ---------------------------------------------------------------------------
// Two-pass fused attention, all-fp16. Pass-1 exp via h2exp (fp16x2 MUFU,
// halves EX2 ops; denominator rounding averages out). Pass-2 exp fp32.
// smem 81920B: Q [0,16384); stage s at 16384+s*32768 (K,V). 2 CTAs/SM.
// ---------------------------------------------------------------------------
__global__ __launch_bounds__(256, 2)
void attn_kernel(const fp16* __restrict__ Qg, const fp16* __restrict__ Kg,
                 const fp16* __restrict__ Vg,
                 float* __restrict__ Ag, fp16* __restrict__ Mg)
{
    extern __shared__ char sm[];
    const unsigned sb = smem_u32(sm);
    const int tid = threadIdx.x, lane = tid & 31, warp = tid >> 5;
    const int bh = blockIdx.y, bb = bh >> 4, hh = bh & 15;
    const int q0 = blockIdx.x * 128;
    const long qrow = (long)bb * NSEQ + q0;
    const fp16* Q = Qg + qrow * DDIM + hh * HDM;
    const fp16* K = Kg + (long)bb * NSEQ * DDIM + hh * HDM;
    const fp16* V = Vg + (long)bb * NSEQ * DDIM + hh * HDM;
    float* Arow = Ag + ((long)bh * NSEQ + q0) * NSEQ;

    const int lrow = lane & 15, lk = (lane >> 4) * 8;

    auto loadQ = [&]() {
        for (int t = tid; t < 1024; t += 256) {
            int r = t >> 3, c = (t & 7) * 8;
            cp16(sb + SWZ(r * 128 + c * 2), Q + (long)r * DDIM + c);
        }
    };
    auto loadK = [&](unsigned dst, int key0) {
        for (int t = tid; t < 1024; t += 256) {
            int r = t >> 3, c = (t & 7) * 8;
            cp16(dst + SWZ(r * 128 + c * 2), K + (long)(key0 + r) * DDIM + c);
        }
    };
    auto loadV = [&](unsigned dst, int key0) {
        for (int t = tid; t < 1024; t += 256) {
            int r = t >> 3, c = (t & 7) * 8;
            cp16(dst + SWZ(r * 128 + c * 2), V + (long)(key0 + r) * DDIM + c);
        }
    };

#define STG(s) (sb + 16384u + (unsigned)(s) * 32768u)

    loadQ();
    loadK(STG(0), 0);
    cp_commit(); cp_wait<0>(); __syncthreads();

    unsigned aq[4][4];
#pragma unroll
    for (int kk = 0; kk < 4; kk++)
        ldm_x4(aq[kk], sb + SWZ((warp*16 + lrow) * 128 + (kk*16 + lk) * 2));

    auto computeS = [&](unsigned kbase, int kg, float (&c)[2][4]) {
#pragma unroll
        for (int kk = 0; kk < 4; kk++) {
            unsigned rh[4];
            ldm_x4(rh, kbase + SWZ((kg*16 + lrow) * 128 + (kk*16 + lk) * 2));
            unsigned b0[2] = {rh[0], rh[2]}, b1[2] = {rh[1], rh[3]};
            mma_fp16(c[0], aq[kk], b0);
            mma_fp16(c[1], aq[kk], b1);
        }
    };

    // ---- pass 1: S -> row sums of exp (h2exp halves MUFU ops) ----
    float lsum0 = 0.f, lsum1 = 0.f;
    for (int kt = 0; kt < 16; kt++) {
        unsigned cur = STG(kt & 1);
        if (kt < 15) {
            loadK(STG((kt + 1) & 1), (kt + 1) * 128);
            cp_commit();
        }
#pragma unroll 1
        for (int kg = 0; kg < 8; kg++) {
            float c[2][4] = {};
            computeS(cur, kg, c);
            float2 e0 = __half22float2(h2exp(__floats2half2_rn(c[0][0]*SM_SCALE, c[0][1]*SM_SCALE)));
            float2 e1 = __half22float2(h2exp(__floats2half2_rn(c[1][0]*SM_SCALE, c[1][1]*SM_SCALE)));
            float2 e2 = __half22float2(h2exp(__floats2half2_rn(c[0][2]*SM_SCALE, c[0][3]*SM_SCALE)));
            float2 e3 = __half22float2(h2exp(__floats2half2_rn(c[1][2]*SM_SCALE, c[1][3]*SM_SCALE)));
            lsum0 += e0.x + e0.y + e1.x + e1.y;
            lsum1 += e2.x + e2.y + e3.x + e3.y;
        }
        if (kt < 15) { cp_wait<0>(); __syncthreads(); }
    }

    lsum0 += __shfl_xor_sync(0xffffffff, lsum0, 1);
    lsum0 += __shfl_xor_sync(0xffffffff, lsum0, 2);
    lsum1 += __shfl_xor_sync(0xffffffff, lsum1, 1);
    lsum1 += __shfl_xor_sync(0xffffffff, lsum1, 2);
    float invl0 = 1.f / lsum0;
    float invl1 = 1.f / lsum1;

    // ---- pass 2: recompute S, fp32 exp, write normalized A, fused PV ----
    __syncthreads();
    loadK(STG(0), 0);
    loadV(STG(0) + 16384, 0);
    cp_commit(); cp_wait<0>(); __syncthreads();

    float Macc[8][4] = {};
    for (int kt = 0; kt < 16; kt++) {
        unsigned stg = STG(kt & 1);
        if (kt < 15) {
            unsigned pre = STG((kt + 1) & 1);
            loadK(pre, (kt + 1) * 128);
            loadV(pre + 16384, (kt + 1) * 128);
            cp_commit();
        }
        unsigned Vs = stg + 16384;
#pragma unroll 1
        for (int kg = 0; kg < 8; kg++) {
            float c[2][4] = {};
            computeS(stg, kg, c);
            float p[2][4];
#pragma unroll
            for (int nj = 0; nj < 2; nj++) {
                p[nj][0] = __expf(c[nj][0] * SM_SCALE) * invl0;
                p[nj][1] = __expf(c[nj][1] * SM_SCALE) * invl0;
                p[nj][2] = __expf(c[nj][2] * SM_SCALE) * invl1;
                p[nj][3] = __expf(c[nj][3] * SM_SCALE) * invl1;
            }
            long colb = (long)kt * 128 + kg * 16 + 2 * (lane & 3);
            long r0 = warp * 16 + (lane >> 2);
            float2 w;
            w.x = p[0][0]; w.y = p[0][1]; *(float2*)&Arow[r0*NSEQ + colb]           = w;
            w.x = p[1][0]; w.y = p[1][1]; *(float2*)&Arow[r0*NSEQ + colb + 8]       = w;
            w.x = p[0][2]; w.y = p[0][3]; *(float2*)&Arow[(r0+8)*NSEQ + colb]       = w;
            w.x = p[1][2]; w.y = p[1][3]; *(float2*)&Arow[(r0+8)*NSEQ + colb + 8]   = w;
            unsigned pa[4];
            pa[0] = pack2h(p[0][0], p[0][1]);
            pa[1] = pack2h(p[0][2], p[0][3]);
            pa[2] = pack2h(p[1][0], p[1][1]);
            pa[3] = pack2h(p[1][2], p[1][3]);
#pragma unroll
            for (int njp = 0; njp < 4; njp++) {
                unsigned bv[4];
                ldm_x4t(bv, Vs + SWZ((kg*16 + lrow) * 128 + ((njp*2 + (lane>>4)) * 8) * 2));
                unsigned b0[2] = {bv[0], bv[1]}, b1[2] = {bv[2], bv[3]};
                mma_fp16(Macc[njp*2],     pa, b0);
                mma_fp16(Macc[njp*2 + 1], pa, b1);
            }
        }
        if (kt < 15) { cp_wait<0>(); __syncthreads(); }
    }

    // ---- epilogue: M -> fp16 ----
    long mrow0 = qrow + warp * 16 + (lane >> 2);
#pragma unroll
    for (int njv = 0; njv < 8; njv++) {
        int col = hh * HDM + njv * 8 + 2 * (lane & 3);
        *(__half2*)&Mg[mrow0 * DDIM + col] =
            __floats2half2_rn(Macc[njv][0], Macc[njv][1]);
        *(__half2*)&Mg[(mrow0 + 8) * DDIM + col] =
            __floats2half2_rn(Macc[njv][2], Macc[njv][3]);
    }
#undef STG
}

// ---------------- elementwise kernels ----------------
__device__ __forceinline__ void conv_body(const float* __restrict__ s,
                                          fp16* __restrict__ d, long i)
{
    float4 v = *(const float4*)(s + i);
    *(__half2*)(d + i)     = __floats2half2_rn(v.x, v.y);
    *(__half2*)(d + i + 2) = __floats2half2_rn(v.z, v.w);
}

__global__ void conv_kernel(const float* __restrict__ s, fp16* __restrict__ d)
{
    long i = ((long)blockIdx.x * blockDim.x + threadIdx.x) * 4;
    conv_body(s, d, i);
}

struct ConvP { const float* s[5]; fp16* d[5]; };
__global__ void conv_multi_kernel(ConvP p)
{
    int z = blockIdx.z;
    long i = ((long)blockIdx.x * blockDim.x + threadIdx.x) * 4;
    conv_body(p.s[z], p.d[z], i);
}

// VG = V16 * G16 (G already post-sigmoid) -> fp16
__global__ void vg_kernel(const fp16* __restrict__ V, const fp16* __restrict__ G,
                          fp16* __restrict__ h)
{
    long i = ((long)blockIdx.x * blockDim.x + threadIdx.x) * 8;
    float4 v = *(const float4*)(V + i);   // 8 halves
    float4 g = *(const float4*)(G + i);
    __half2* vp = (__half2*)&v;
    __half2* gp = (__half2*)&g;
    float4 o;
    __half2* op = (__half2*)&o;
#pragma unroll
    for (int j = 0; j < 4; j++) op[j] = __hmul2(vp[j], gp[j]);
    *(float4*)(h + i) = o;
}

// LayerNorm over last dim (1024)
__global__ void ln_kernel(const float* __restrict__ Y,
                          const float* __restrict__ gamma,
                          const float* __restrict__ beta,
                          float* __restrict__ out)
{
    __shared__ float red[256];
    int row = blockIdx.x, tid = threadIdx.x;
    const float4* y4 = (const float4*)(Y + (long)row * DDIM);
    float4 v = y4[tid];

    red[tid] = v.x + v.y + v.z + v.w; __syncthreads();
    for (int o = 128; o > 0; o >>= 1) {
        if (tid < o) red[tid] += red[tid + o];
        __syncthreads();
    }
    float mean = red[0] * (1.f / DDIM);
    __syncthreads();

    float d0 = v.x - mean, d1 = v.y - mean, d2 = v.z - mean, d3 = v.w - mean;
    red[tid] = d0*d0 + d1*d1 + d2*d2 + d3*d3; __syncthreads();
    for (int o = 128; o > 0; o >>= 1) {
        if (tid < o) red[tid] += red[tid + o];
        __syncthreads();
    }
    float var = red[0] * (1.f / DDIM);
    float inv = rsqrtf(var + 1e-5f);

    float4 g  = ((const float4*)gamma)[tid];
    float4 bt = ((const float4*)beta)[tid];
    float4 o4;
    o4.x = g.x * (d0 * inv) + bt.x;
    o4.y = g.y * (d1 * inv) + bt.y;
    o4.z = g.z * (d2 * inv) + bt.z;
    o4.w = g.w * (d3 * inv) + bt.w;
    ((float4*)(out + (long)row * DDIM))[tid] = o4;
}

extern "C" void kernel_launch(void* const* d_in, const int* in_sizes, int n_in,
                              void* d_out, int out_size)
{
    const float* x     = (const float*)d_in[0];
    const float* Wq    = (const float*)d_in[1];
    const float* bq    = (const float*)d_in[2];
    const float* Wk    = (const float*)d_in[3];
    const float* bk    = (const float*)d_in[4];
    const float* Wv    = (const float*)d_in[5];
    const float* bv    = (const float*)d_in[6];
    const float* Wg    = (const float*)d_in[7];
    const float* bg    = (const float*)d_in[8];
    const float* Wp    = (const float*)d_in[9];
    const float* bp    = (const float*)d_in[10];
    const float* gamma = (const float*)d_in[11];
    const float* beta  = (const float*)d_in[12];
    float* outp = (float*)d_out;

    fp16 *x16, *w16, *Q16, *K16, *V16, *G16, *VG16, *M16;
    float *Y, *Afb;
    cudaGetSymbolAddress((void**)&x16,  g_x16);
    cudaGetSymbolAddress((void**)&w16,  g_w16);
    cudaGetSymbolAddress((void**)&Q16,  g_Q16);
    cudaGetSymbolAddress((void**)&K16,  g_K16);
    cudaGetSymbolAddress((void**)&V16,  g_V16);
    cudaGetSymbolAddress((void**)&G16,  g_G16);
    cudaGetSymbolAddress((void**)&VG16, g_VG16);
    cudaGetSymbolAddress((void**)&M16,  g_M16);
    cudaGetSymbolAddress((void**)&Y,    g_Y);
    cudaGetSymbolAddress((void**)&Afb,  g_Afb);

    float* A = ((long)out_size >= OUT1 + AELEMS) ? (outp + OUT1) : Afb;

    const long WSZ = (long)LDIM * DDIM;
    const long XHALF = (long)BNROWS * LDIM / 2;

    // launches 0-1: x -> fp16 (two halves, keeps attn at ncu launch index 5)
    conv_kernel<<<XHALF/1024, 256>>>(x, x16);
    conv_kernel<<<XHALF/1024, 256>>>(x + XHALF, x16 + XHALF);

    // launch 2: all 5 weights -> fp16
    {
        ConvP p;
        p.s[0] = Wq; p.d[0] = w16 + 0*WSZ;
        p.s[1] = Wk; p.d[1] = w16 + 1*WSZ;
        p.s[2] = Wv; p.d[2] = w16 + 2*WSZ;
        p.s[3] = Wg; p.d[3] = w16 + 3*WSZ;
        p.s[4] = Wp; p.d[4] = w16 + 4*WSZ;
        dim3 g(WSZ/1024, 1, 5);
        conv_multi_kernel<<<g, 256>>>(p);
    }

    constexpr int SM_PROJ = 2 * stage_bytes_h(128, 128, 32);   // 37888
    constexpr int SM_ATTN = 81920;

    cudaFuncSetAttribute(gemm4_kernel<128,128,32,64,32>,
                         cudaFuncAttributeMaxDynamicSharedMemorySize, SM_PROJ);
    cudaFuncSetAttribute(gemm1_kernel<128,128,32,64,32>,
                         cudaFuncAttributeMaxDynamicSharedMemorySize, SM_PROJ);
    cudaFuncSetAttribute(attn_kernel,
                         cudaFuncAttributeMaxDynamicSharedMemorySize, SM_ATTN);

    // launch 3: fused fp16 projections (Q, K, V, sigmoid-G), 64x32 warp tiles
    {
        Ptrs4 p;
        p.B16[0] = w16 + 0*WSZ; p.bias[0] = bq; p.C16[0] = Q16; p.act[0] = 0;
        p.B16[1] = w16 + 1*WSZ; p.bias[1] = bk; p.C16[1] = K16; p.act[1] = 0;
        p.B16[2] = w16 + 2*WSZ; p.bias[2] = bv; p.C16[2] = V16; p.act[2] = 0;
        p.B16[3] = w16 + 3*WSZ; p.bias[3] = bg; p.C16[3] = G16; p.act[3] = 1;
        dim3 grid(DDIM/128, BNROWS/128, 4);
        gemm4_kernel<128,128,32,64,32><<<grid, 256, SM_PROJ>>>(
            LDIM, x16, LDIM, DDIM, DDIM, p);
    }

    // launch 4: VG = V * G
    vg_kernel<<<(BNROWS*(long)DDIM)/2048, 256>>>(V16, G16, VG16);

    // launch 5: two-pass fp16 attention (ncu -s 5 lands here)
    {
        dim3 grid(NSEQ/128, BDIM*HH);
        attn_kernel<<<grid, 256, SM_ATTN>>>(Q16, K16, VG16, A, M16);
    }

    // launch 6: Y = x + M @ Wp + bp
    {
        dim3 grid(DDIM/128, BNROWS/128, 1);
        gemm1_kernel<128,128,32,64,32><<<grid, 256, SM_PROJ>>>(
            DDIM, M16, DDIM, w16 + 4*WSZ, DDIM,
            Y, DDIM, bp, x, DDIM);
    }

    // launch 7: LayerNorm -> out
    ln_kernel<<<BNROWS, 256>>>(Y, gamma, beta, outp);
}

// round 15
// speedup vs baseline: 1.0942x; 1.0729x over previous
#include <cuda_runtime.h>
#include <cuda_fp16.h>
#include <math.h>

#define BDIM 2
#define NSEQ 2048
#define LDIM 1024
#define DDIM 1024
#define HH   16
#define HDM  64
#define BNROWS (BDIM*NSEQ)   // 4096
#define SM_SCALE 0.125f

static const long OUT1   = (long)BDIM * NSEQ * DDIM;        // 4,194,304
static const long AELEMS = (long)BDIM * HH * NSEQ * NSEQ;   // 134,217,728

typedef __half fp16;

// ---------------- device scratch (no cudaMalloc anywhere) ----------------
__device__ __align__(256) fp16 g_x16[BNROWS*LDIM];
__device__ __align__(256) fp16 g_w16[5][LDIM*DDIM];
__device__ __align__(256) fp16 g_Q16[BNROWS*DDIM];
__device__ __align__(256) fp16 g_K16[BNROWS*DDIM];
__device__ __align__(256) fp16 g_V16[BNROWS*DDIM];
__device__ __align__(256) fp16 g_G16[BNROWS*DDIM];
__device__ __align__(256) fp16 g_VG16[BNROWS*DDIM];
__device__ __align__(256) fp16 g_M16[BNROWS*DDIM];
__device__ float g_Y[BNROWS*DDIM];
__device__ float g_Afb[(size_t)BDIM*HH*NSEQ*NSEQ];  // fallback if A not in output

// ---------------- PTX helpers ----------------
__device__ __forceinline__ unsigned smem_u32(const void* p) {
    return (unsigned)__cvta_generic_to_shared(p);
}
__device__ __forceinline__ void cp16(unsigned dst, const void* src) {
    asm volatile("cp.async.ca.shared.global [%0], [%1], 16;\n" :: "r"(dst), "l"(src));
}
__device__ __forceinline__ void cp_commit() { asm volatile("cp.async.commit_group;\n" ::); }
template<int N> __device__ __forceinline__ void cp_wait() {
    asm volatile("cp.async.wait_group %0;\n" :: "n"(N));
}
__device__ __forceinline__ void ldm_x4(unsigned* d, unsigned addr) {
    asm volatile("ldmatrix.sync.aligned.m8n8.x4.shared.b16 {%0,%1,%2,%3}, [%4];"
                 : "=r"(d[0]), "=r"(d[1]), "=r"(d[2]), "=r"(d[3]) : "r"(addr));
}
__device__ __forceinline__ void ldm_x4t(unsigned* d, unsigned addr) {
    asm volatile("ldmatrix.sync.aligned.m8n8.x4.trans.shared.b16 {%0,%1,%2,%3}, [%4];"
                 : "=r"(d[0]), "=r"(d[1]), "=r"(d[2]), "=r"(d[3]) : "r"(addr));
}
__device__ __forceinline__ void mma_fp16(float* c, const unsigned* a, const unsigned* b) {
    asm volatile(
        "mma.sync.aligned.m16n8k16.row.col.f32.f16.f16.f32 "
        "{%0,%1,%2,%3},{%4,%5,%6,%7},{%8,%9},{%0,%1,%2,%3};"
        : "+f"(c[0]), "+f"(c[1]), "+f"(c[2]), "+f"(c[3])
        : "r"(a[0]), "r"(a[1]), "r"(a[2]), "r"(a[3]), "r"(b[0]), "r"(b[1]));
}
__device__ __forceinline__ unsigned pack2h(float a, float b) {
    __half2 t = __floats2half2_rn(a, b);
    return *(unsigned*)&t;
}
// streaming (evict-first) 8-byte store: keep A writes from thrashing L2
__device__ __forceinline__ void stcs2(float* p, float a, float b) {
    float2 v; v.x = a; v.y = b;
    __stcs((float2*)p, v);
}

// SW128 XOR swizzle (byte offsets within a 1024B-aligned 128B-row tile)
#define SWZ(o) ((unsigned)(o) ^ ((((unsigned)(o)) >> 3) & 0x70))

// ---------------------------------------------------------------------------
// GEMM body: fp16 tensor-core GEMM, warp tile 64x32, BK=64 (half the barriers
// of BK=32), cp.async 2-stage, one sync/chunk.
// ---------------------------------------------------------------------------
template<int BM, int BN, int BK, int WM, int WN, int THREADS>
__device__ __forceinline__ void gemm_body(
    int K,
    const fp16* __restrict__ Ag, int lda,
    const fp16* __restrict__ Bg, int ldb,
    float* Cf, fp16* C16, int ldc,
    const float* bias, const float* resid, int ldr, int act)
{
    constexpr int APITCH = BK + 8;
    constexpr int BPITCH = BN + 8;
    constexpr int ABYTES = BM * APITCH * 2;
    constexpr int BBYTES = BK * BPITCH * 2;
    constexpr int STAGE  = ABYTES + BBYTES;
    constexpr int MI = WM / 16, NJ = WN / 8;

    extern __shared__ char dsm[];

    const int tid  = threadIdx.x;
    const int lane = tid & 31;
    const int warp = tid >> 5;
    const int wm = warp % (BM/WM);
    const int wn = warp / (BM/WM);
    const int m0 = wm * WM, n0 = wn * WN;
    const int rowBase = blockIdx.y * BM;
    const int colBase = blockIdx.x * BN;
    const int lrow  = lane & 15;
    const int lkoff = (lane >> 4) << 3;

    float acc[MI][NJ][4];
#pragma unroll
    for (int i = 0; i < MI; i++)
#pragma unroll
        for (int j = 0; j < NJ; j++)
#pragma unroll
            for (int q = 0; q < 4; q++) acc[i][j][q] = 0.f;

    auto load_stage = [&](int s, int k0) {
        char* base = dsm + s * STAGE;
        fp16* As = (fp16*)(base);
        fp16* Bs = (fp16*)(base + ABYTES);
        constexpr int ACH = BM * BK / 8;
#pragma unroll
        for (int t = 0; t < ACH; t += THREADS) {
            int idx = t + tid;
            int r = idx / (BK/8);
            int c = (idx % (BK/8)) * 8;
            cp16(smem_u32(As + r*APITCH + c), Ag + (long)(rowBase + r) * lda + k0 + c);
        }
        constexpr int BCH = BK * BN / 8;
#pragma unroll
        for (int t = 0; t < BCH; t += THREADS) {
            int idx = t + tid;
            int r = idx / (BN/8);
            int c = (idx % (BN/8)) * 8;
            cp16(smem_u32(Bs + r*BPITCH + c), Bg + (long)(k0 + r) * ldb + colBase + c);
        }
    };

    auto compute_stage = [&](int s) {
        char* base = dsm + s * STAGE;
        fp16* As = (fp16*)(base);
        fp16* Bs = (fp16*)(base + ABYTES);
#pragma unroll
        for (int kk = 0; kk < BK; kk += 16) {
            unsigned af[MI][4];
            unsigned bf[NJ][2];
#pragma unroll
            for (int mi = 0; mi < MI; mi++)
                ldm_x4(af[mi], smem_u32(As + (m0 + mi*16 + lrow)*APITCH + kk + lkoff));
#pragma unroll
            for (int nj = 0; nj < NJ; nj += 2)
                ldm_x4t(&bf[nj][0], smem_u32(Bs + (kk + lrow)*BPITCH + n0 + (nj + (lane>>4))*8));
#pragma unroll
            for (int mi = 0; mi < MI; mi++)
#pragma unroll
                for (int nj = 0; nj < NJ; nj++)
                    mma_fp16(acc[mi][nj], af[mi], bf[nj]);
        }
    };

    const int KT = K / BK;
    load_stage(0, 0);
    cp_commit();
    for (int kt = 0; kt < KT; kt++) {
        cp_wait<0>();
        __syncthreads();
        if (kt + 1 < KT) {
            load_stage((kt + 1) & 1, (kt + 1) * BK);
            cp_commit();
        }
        compute_stage(kt & 1);
    }

    // ---- epilogue ----
#pragma unroll
    for (int mi = 0; mi < MI; mi++) {
#pragma unroll
        for (int nj = 0; nj < NJ; nj++) {
            int c = colBase + n0 + nj*8 + 2*(lane & 3);
            float b0 = 0.f, b1 = 0.f;
            if (bias) { b0 = bias[c]; b1 = bias[c+1]; }
#pragma unroll
            for (int half = 0; half < 2; half++) {
                int r = rowBase + m0 + mi*16 + (lane >> 2) + half*8;
                float v0 = acc[mi][nj][half*2+0] + b0;
                float v1 = acc[mi][nj][half*2+1] + b1;
                if (act == 1) {
                    v0 = 1.f / (1.f + __expf(-v0));
                    v1 = 1.f / (1.f + __expf(-v1));
                }
                if (resid) {
                    v0 += resid[(long)r * ldr + c];
                    v1 += resid[(long)r * ldr + c + 1];
                }
                long off = (long)r * ldc + c;
                if (Cf) {
                    float2 o; o.x = v0; o.y = v1;
                    *(float2*)&Cf[off] = o;
                }
                if (C16) {
                    *(__half2*)&C16[off] = __floats2half2_rn(v0, v1);
                }
            }
        }
    }
}

// multiplexed 4-projection kernel (all-fp16)
struct Ptrs4 {
    const fp16* B16[4];
    const float* bias[4];
    fp16* C16[4];
    int act[4];
};

template<int BM, int BN, int BK, int WM, int WN>
__global__ __launch_bounds__((BM/WM)*(BN/WN)*32, 2)
void gemm4_kernel(int K, const fp16* __restrict__ A16,
                  int lda, int ldb, int ldc, Ptrs4 p)
{
    int z = blockIdx.z;
    gemm_body<BM,BN,BK,WM,WN,(BM/WM)*(BN/WN)*32>(
        K, A16, lda, p.B16[z], ldb,
        nullptr, p.C16[z], ldc, p.bias[z], nullptr, 0, p.act[z]);
}

// single GEMM (out projection): fp32 output + bias + residual
template<int BM, int BN, int BK, int WM, int WN>
__global__ __launch_bounds__((BM/WM)*(BN/WN)*32, 2)
void gemm1_kernel(int K,
                  const fp16* __restrict__ A16, int lda,
                  const fp16* __restrict__ B16, int ldb,
                  float* Cf, int ldc,
                  const float* bias, const float* resid, int ldr)
{
    gemm_body<BM,BN,BK,WM,WN,(BM/WM)*(BN/WN)*32>(
        K, A16, lda, B16, ldb,
        Cf, nullptr, ldc, bias, resid, ldr, 0);
}

constexpr int stage_bytes_h(int BM, int BN, int BK) {
    return (BM * (BK + 8) * 2) + (BK * (BN + 8) * 2);
}

// ---------------------------------------------------------------------------
// Two-pass fused attention, all-fp16 (round-12 numerics exactly; fp32 exp in
// both passes). A stores use __stcs (evict-first) so the 537MB stream doesn't
// thrash K/V out of L2. smem 81920B: Q [0,16384); stage s at 16384+s*32768.
// ---------------------------------------------------------------------------
__global__ __launch_bounds__(256, 2)
void attn_kernel(const fp16* __restrict__ Qg, const fp16* __restrict__ Kg,
                 const fp16* __restrict__ Vg,
                 float* __restrict__ Ag, fp16* __restrict__ Mg)
{
    extern __shared__ char sm[];
    const unsigned sb = smem_u32(sm);
    const int tid = threadIdx.x, lane = tid & 31, warp = tid >> 5;
    const int bh = blockIdx.y, bb = bh >> 4, hh = bh & 15;
    const int q0 = blockIdx.x * 128;
    const long qrow = (long)bb * NSEQ + q0;
    const fp16* Q = Qg + qrow * DDIM + hh * HDM;
    const fp16* K = Kg + (long)bb * NSEQ * DDIM + hh * HDM;
    const fp16* V = Vg + (long)bb * NSEQ * DDIM + hh * HDM;
    float* Arow = Ag + ((long)bh * NSEQ + q0) * NSEQ;

    const int lrow = lane & 15, lk = (lane >> 4) * 8;

    auto loadQ = [&]() {
        for (int t = tid; t < 1024; t += 256) {
            int r = t >> 3, c = (t & 7) * 8;
            cp16(sb + SWZ(r * 128 + c * 2), Q + (long)r * DDIM + c);
        }
    };
    auto loadK = [&](unsigned dst, int key0) {
        for (int t = tid; t < 1024; t += 256) {
            int r = t >> 3, c = (t & 7) * 8;
            cp16(dst + SWZ(r * 128 + c * 2), K + (long)(key0 + r) * DDIM + c);
        }
    };
    auto loadV = [&](unsigned dst, int key0) {
        for (int t = tid; t < 1024; t += 256) {
            int r = t >> 3, c = (t & 7) * 8;
            cp16(dst + SWZ(r * 128 + c * 2), V + (long)(key0 + r) * DDIM + c);
        }
    };

#define STG(s) (sb + 16384u + (unsigned)(s) * 32768u)

    loadQ();
    loadK(STG(0), 0);
    cp_commit(); cp_wait<0>(); __syncthreads();

    unsigned aq[4][4];
#pragma unroll
    for (int kk = 0; kk < 4; kk++)
        ldm_x4(aq[kk], sb + SWZ((warp*16 + lrow) * 128 + (kk*16 + lk) * 2));

    auto computeS = [&](unsigned kbase, int kg, float (&c)[2][4]) {
#pragma unroll
        for (int kk = 0; kk < 4; kk++) {
            unsigned rh[4];
            ldm_x4(rh, kbase + SWZ((kg*16 + lrow) * 128 + (kk*16 + lk) * 2));
            unsigned b0[2] = {rh[0], rh[2]}, b1[2] = {rh[1], rh[3]};
            mma_fp16(c[0], aq[kk], b0);
            mma_fp16(c[1], aq[kk], b1);
        }
    };

    // ---- pass 1: S -> row sums of exp (fp32 exp, round-12 numerics) ----
    float lsum0 = 0.f, lsum1 = 0.f;
    for (int kt = 0; kt < 16; kt++) {
        unsigned cur = STG(kt & 1);
        if (kt < 15) {
            loadK(STG((kt + 1) & 1), (kt + 1) * 128);
            cp_commit();
        }
#pragma unroll 1
        for (int kg = 0; kg < 8; kg++) {
            float c[2][4] = {};
            computeS(cur, kg, c);
            lsum0 += __expf(c[0][0]*SM_SCALE) + __expf(c[0][1]*SM_SCALE)
                   + __expf(c[1][0]*SM_SCALE) + __expf(c[1][1]*SM_SCALE);
            lsum1 += __expf(c[0][2]*SM_SCALE) + __expf(c[0][3]*SM_SCALE)
                   + __expf(c[1][2]*SM_SCALE) + __expf(c[1][3]*SM_SCALE);
        }
        if (kt < 15) { cp_wait<0>(); __syncthreads(); }
    }

    lsum0 += __shfl_xor_sync(0xffffffff, lsum0, 1);
    lsum0 += __shfl_xor_sync(0xffffffff, lsum0, 2);
    lsum1 += __shfl_xor_sync(0xffffffff, lsum1, 1);
    lsum1 += __shfl_xor_sync(0xffffffff, lsum1, 2);
    float invl0 = 1.f / lsum0;
    float invl1 = 1.f / lsum1;

    // ---- pass 2: recompute S, fp32 exp, write normalized A (__stcs), PV ----
    __syncthreads();
    loadK(STG(0), 0);
    loadV(STG(0) + 16384, 0);
    cp_commit(); cp_wait<0>(); __syncthreads();

    float Macc[8][4] = {};
    for (int kt = 0; kt < 16; kt++) {
        unsigned stg = STG(kt & 1);
        if (kt < 15) {
            unsigned pre = STG((kt + 1) & 1);
            loadK(pre, (kt + 1) * 128);
            loadV(pre + 16384, (kt + 1) * 128);
            cp_commit();
        }
        unsigned Vs = stg + 16384;
#pragma unroll 1
        for (int kg = 0; kg < 8; kg++) {
            float c[2][4] = {};
            computeS(stg, kg, c);
            float p[2][4];
#pragma unroll
            for (int nj = 0; nj < 2; nj++) {
                p[nj][0] = __expf(c[nj][0] * SM_SCALE) * invl0;
                p[nj][1] = __expf(c[nj][1] * SM_SCALE) * invl0;
                p[nj][2] = __expf(c[nj][2] * SM_SCALE) * invl1;
                p[nj][3] = __expf(c[nj][3] * SM_SCALE) * invl1;
            }
            long colb = (long)kt * 128 + kg * 16 + 2 * (lane & 3);
            long r0 = warp * 16 + (lane >> 2);
            stcs2(&Arow[r0*NSEQ + colb],         p[0][0], p[0][1]);
            stcs2(&Arow[r0*NSEQ + colb + 8],     p[1][0], p[1][1]);
            stcs2(&Arow[(r0+8)*NSEQ + colb],     p[0][2], p[0][3]);
            stcs2(&Arow[(r0+8)*NSEQ + colb + 8], p[1][2], p[1][3]);
            unsigned pa[4];
            pa[0] = pack2h(p[0][0], p[0][1]);
            pa[1] = pack2h(p[0][2], p[0][3]);
            pa[2] = pack2h(p[1][0], p[1][1]);
            pa[3] = pack2h(p[1][2], p[1][3]);
#pragma unroll
            for (int njp = 0; njp < 4; njp++) {
                unsigned bv[4];
                ldm_x4t(bv, Vs + SWZ((kg*16 + lrow) * 128 + ((njp*2 + (lane>>4)) * 8) * 2));
                unsigned b0[2] = {bv[0], bv[1]}, b1[2] = {bv[2], bv[3]};
                mma_fp16(Macc[njp*2],     pa, b0);
                mma_fp16(Macc[njp*2 + 1], pa, b1);
            }
        }
        if (kt < 15) { cp_wait<0>(); __syncthreads(); }
    }

    // ---- epilogue: M -> fp16 ----
    long mrow0 = qrow + warp * 16 + (lane >> 2);
#pragma unroll
    for (int njv = 0; njv < 8; njv++) {
        int col = hh * HDM + njv * 8 + 2 * (lane & 3);
        *(__half2*)&Mg[mrow0 * DDIM + col] =
            __floats2half2_rn(Macc[njv][0], Macc[njv][1]);
        *(__half2*)&Mg[(mrow0 + 8) * DDIM + col] =
            __floats2half2_rn(Macc[njv][2], Macc[njv][3]);
    }
#undef STG
}

// ---------------- elementwise kernels ----------------
__device__ __forceinline__ void conv_body(const float* __restrict__ s,
                                          fp16* __restrict__ d, long i)
{
    float4 v = *(const float4*)(s + i);
    *(__half2*)(d + i)     = __floats2half2_rn(v.x, v.y);
    *(__half2*)(d + i + 2) = __floats2half2_rn(v.z, v.w);
}

__global__ void conv_kernel(const float* __restrict__ s, fp16* __restrict__ d)
{
    long i = ((long)blockIdx.x * blockDim.x + threadIdx.x) * 4;
    conv_body(s, d, i);
}

struct ConvP { const float* s[5]; fp16* d[5]; };
__global__ void conv_multi_kernel(ConvP p)
{
    int z = blockIdx.z;
    long i = ((long)blockIdx.x * blockDim.x + threadIdx.x) * 4;
    conv_body(p.s[z], p.d[z], i);
}

// VG = V16 * G16 (G already post-sigmoid) -> fp16
__global__ void vg_kernel(const fp16* __restrict__ V, const fp16* __restrict__ G,
                          fp16* __restrict__ h)
{
    long i = ((long)blockIdx.x * blockDim.x + threadIdx.x) * 8;
    float4 v = *(const float4*)(V + i);   // 8 halves
    float4 g = *(const float4*)(G + i);
    __half2* vp = (__half2*)&v;
    __half2* gp = (__half2*)&g;
    float4 o;
    __half2* op = (__half2*)&o;
#pragma unroll
    for (int j = 0; j < 4; j++) op[j] = __hmul2(vp[j], gp[j]);
    *(float4*)(h + i) = o;
}

// LayerNorm over last dim (1024)
__global__ void ln_kernel(const float* __restrict__ Y,
                          const float* __restrict__ gamma,
                          const float* __restrict__ beta,
                          float* __restrict__ out)
{
    __shared__ float red[256];
    int row = blockIdx.x, tid = threadIdx.x;
    const float4* y4 = (const float4*)(Y + (long)row * DDIM);
    float4 v = y4[tid];

    red[tid] = v.x + v.y + v.z + v.w; __syncthreads();
    for (int o = 128; o > 0; o >>= 1) {
        if (tid < o) red[tid] += red[tid + o];
        __syncthreads();
    }
    float mean = red[0] * (1.f / DDIM);
    __syncthreads();

    float d0 = v.x - mean, d1 = v.y - mean, d2 = v.z - mean, d3 = v.w - mean;
    red[tid] = d0*d0 + d1*d1 + d2*d2 + d3*d3; __syncthreads();
    for (int o = 128; o > 0; o >>= 1) {
        if (tid < o) red[tid] += red[tid + o];
        __syncthreads();
    }
    float var = red[0] * (1.f / DDIM);
    float inv = rsqrtf(var + 1e-5f);

    float4 g  = ((const float4*)gamma)[tid];
    float4 bt = ((const float4*)beta)[tid];
    float4 o4;
    o4.x = g.x * (d0 * inv) + bt.x;
    o4.y = g.y * (d1 * inv) + bt.y;
    o4.z = g.z * (d2 * inv) + bt.z;
    o4.w = g.w * (d3 * inv) + bt.w;
    ((float4*)(out + (long)row * DDIM))[tid] = o4;
}

extern "C" void kernel_launch(void* const* d_in, const int* in_sizes, int n_in,
                              void* d_out, int out_size)
{
    const float* x     = (const float*)d_in[0];
    const float* Wq    = (const float*)d_in[1];
    const float* bq    = (const float*)d_in[2];
    const float* Wk    = (const float*)d_in[3];
    const float* bk    = (const float*)d_in[4];
    const float* Wv    = (const float*)d_in[5];
    const float* bv    = (const float*)d_in[6];
    const float* Wg    = (const float*)d_in[7];
    const float* bg    = (const float*)d_in[8];
    const float* Wp    = (const float*)d_in[9];
    const float* bp    = (const float*)d_in[10];
    const float* gamma = (const float*)d_in[11];
    const float* beta  = (const float*)d_in[12];
    float* outp = (float*)d_out;

    fp16 *x16, *w16, *Q16, *K16, *V16, *G16, *VG16, *M16;
    float *Y, *Afb;
    cudaGetSymbolAddress((void**)&x16,  g_x16);
    cudaGetSymbolAddress((void**)&w16,  g_w16);
    cudaGetSymbolAddress((void**)&Q16,  g_Q16);
    cudaGetSymbolAddress((void**)&K16,  g_K16);
    cudaGetSymbolAddress((void**)&V16,  g_V16);
    cudaGetSymbolAddress((void**)&G16,  g_G16);
    cudaGetSymbolAddress((void**)&VG16, g_VG16);
    cudaGetSymbolAddress((void**)&M16,  g_M16);
    cudaGetSymbolAddress((void**)&Y,    g_Y);
    cudaGetSymbolAddress((void**)&Afb,  g_Afb);

    float* A = ((long)out_size >= OUT1 + AELEMS) ? (outp + OUT1) : Afb;

    const long WSZ = (long)LDIM * DDIM;
    const long XHALF = (long)BNROWS * LDIM / 2;

    // launches 0-1: x -> fp16 (two halves)
    conv_kernel<<<XHALF/1024, 256>>>(x, x16);
    conv_kernel<<<XHALF/1024, 256>>>(x + XHALF, x16 + XHALF);

    // launch 2: all 5 weights -> fp16
    {
        ConvP p;
        p.s[0] = Wq; p.d[0] = w16 + 0*WSZ;
        p.s[1] = Wk; p.d[1] = w16 + 1*WSZ;
        p.s[2] = Wv; p.d[2] = w16 + 2*WSZ;
        p.s[3] = Wg; p.d[3] = w16 + 3*WSZ;
        p.s[4] = Wp; p.d[4] = w16 + 4*WSZ;
        dim3 g(WSZ/1024, 1, 5);
        conv_multi_kernel<<<g, 256>>>(p);
    }

    constexpr int SM_PROJ = 2 * stage_bytes_h(128, 128, 64);   // 71680
    constexpr int SM_ATTN = 81920;

    cudaFuncSetAttribute(gemm4_kernel<128,128,64,64,32>,
                         cudaFuncAttributeMaxDynamicSharedMemorySize, SM_PROJ);
    cudaFuncSetAttribute(gemm1_kernel<128,128,64,64,32>,
                         cudaFuncAttributeMaxDynamicSharedMemorySize, SM_PROJ);
    cudaFuncSetAttribute(attn_kernel,
                         cudaFuncAttributeMaxDynamicSharedMemorySize, SM_ATTN);

    // launch 3: fused fp16 projections (Q, K, V, sigmoid-G), BK=64
    {
        Ptrs4 p;
        p.B16[0] = w16 + 0*WSZ; p.bias[0] = bq; p.C16[0] = Q16; p.act[0] = 0;
        p.B16[1] = w16 + 1*WSZ; p.bias[1] = bk; p.C16[1] = K16; p.act[1] = 0;
        p.B16[2] = w16 + 2*WSZ; p.bias[2] = bv; p.C16[2] = V16; p.act[2] = 0;
        p.B16[3] = w16 + 3*WSZ; p.bias[3] = bg; p.C16[3] = G16; p.act[3] = 1;
        dim3 grid(DDIM/128, BNROWS/128, 4);
        gemm4_kernel<128,128,64,64,32><<<grid, 256, SM_PROJ>>>(
            LDIM, x16, LDIM, DDIM, DDIM, p);
    }

    // launch 4: VG = V * G
    vg_kernel<<<(BNROWS*(long)DDIM)/2048, 256>>>(V16, G16, VG16);

    // launch 5: two-pass fp16 attention
    {
        dim3 grid(NSEQ/128, BDIM*HH);
        attn_kernel<<<grid, 256, SM_ATTN>>>(Q16, K16, VG16, A, M16);
    }

    // launch 6: Y = x + M @ Wp + bp, BK=64
    {
        dim3 grid(DDIM/128, BNROWS/128, 1);
        gemm1_kernel<128,128,64,64,32><<<grid, 256, SM_PROJ>>>(
            DDIM, M16, DDIM, w16 + 4*WSZ, DDIM,
            Y, DDIM, bp, x, DDIM);
    }

    // launch 7: LayerNorm -> out
    ln_kernel<<<BNROWS, 256>>>(Y, gamma, beta, outp);
}